// round 2
// baseline (speedup 1.0000x reference)
#include <cuda_runtime.h>
#include <math.h>

// Problem constants
constexpr int B_  = 8;
constexpr int C_  = 512;
constexpr int H_  = 96;
constexpr int W_  = 96;
constexpr int N_  = H_ * W_;   // 9216
constexpr int O3  = 3 * C_;    // 1536

// Scratch (device globals: allocation-free per harness rules)
// qkv: [B, 3C, N] = 453 MB ; attn: [B, C, C] = 8 MB
__device__ float g_qkv[(size_t)B_ * O3 * N_];
__device__ float g_attn[(size_t)B_ * C_ * C_];

#define BM 128
#define BN 128
#define BK 16
#define TM 8
#define TN 8

// C[M,N] = A[M,K] * B  (+bias[M])
// TRANSB=false: B is [K,N] row-major (row stride == N)
// TRANSB=true : B is [N,K] row-major (row stride == K)  => C = A * B^T
template<bool TRANSB, bool HASBIAS>
__global__ __launch_bounds__(256)
void gemm_kernel(const float* __restrict__ A, const float* __restrict__ B,
                 float* __restrict__ C, const float* __restrict__ bias,
                 int M, int N, int K,
                 size_t sA, size_t sB, size_t sC)
{
    __shared__ float As[BK][BM];
    __shared__ float Bs[BK][BN];

    const float* Ap = A + (size_t)blockIdx.z * sA;
    const float* Bp = B + (size_t)blockIdx.z * sB;
    float*       Cp = C + (size_t)blockIdx.z * sC;

    const int tm  = blockIdx.y * BM;
    const int tn  = blockIdx.x * BN;
    const int tid = threadIdx.x;
    const int tx  = tid & 15;   // 0..15 -> N direction
    const int ty  = tid >> 4;   // 0..15 -> M direction

    float acc[TM][TN];
    #pragma unroll
    for (int i = 0; i < TM; i++)
        #pragma unroll
        for (int j = 0; j < TN; j++)
            acc[i][j] = 0.f;

    for (int k0 = 0; k0 < K; k0 += BK) {
        // ---- load A tile [BM x BK], store transposed As[k][m] ----
        #pragma unroll
        for (int l = 0; l < 2; l++) {
            int f   = tid + l * 256;       // 0..511 float4 id
            int row = f >> 2;              // 0..127
            int kc  = (f & 3) << 2;        // 0,4,8,12
            float4 v = *reinterpret_cast<const float4*>(
                &Ap[(size_t)(tm + row) * K + k0 + kc]);
            As[kc + 0][row] = v.x;
            As[kc + 1][row] = v.y;
            As[kc + 2][row] = v.z;
            As[kc + 3][row] = v.w;
        }
        // ---- load B tile ----
        if (TRANSB) {
            // B is [N,K]: tile [BN x BK], transpose into Bs[k][n]
            #pragma unroll
            for (int l = 0; l < 2; l++) {
                int f   = tid + l * 256;
                int row = f >> 2;          // n index 0..127
                int kc  = (f & 3) << 2;
                float4 v = *reinterpret_cast<const float4*>(
                    &Bp[(size_t)(tn + row) * K + k0 + kc]);
                Bs[kc + 0][row] = v.x;
                Bs[kc + 1][row] = v.y;
                Bs[kc + 2][row] = v.z;
                Bs[kc + 3][row] = v.w;
            }
        } else {
            // B is [K,N]: tile [BK x BN], direct copy
            #pragma unroll
            for (int l = 0; l < 2; l++) {
                int f   = tid + l * 256;
                int row = f >> 5;          // k 0..15
                int col = (f & 31) << 2;   // n 0..124
                float4 v = *reinterpret_cast<const float4*>(
                    &Bp[(size_t)(k0 + row) * N + tn + col]);
                *reinterpret_cast<float4*>(&Bs[row][col]) = v;
            }
        }
        __syncthreads();

        // ---- compute ----
        #pragma unroll
        for (int kk = 0; kk < BK; kk++) {
            float ra[TM], rb[TN];
            #pragma unroll
            for (int i = 0; i < TM; i++) ra[i] = As[kk][ty * TM + i];
            #pragma unroll
            for (int j = 0; j < TN; j++) rb[j] = Bs[kk][tx * TN + j];
            #pragma unroll
            for (int i = 0; i < TM; i++)
                #pragma unroll
                for (int j = 0; j < TN; j++)
                    acc[i][j] += ra[i] * rb[j];
        }
        __syncthreads();
    }

    // ---- epilogue: bias + store ----
    #pragma unroll
    for (int i = 0; i < TM; i++) {
        int row  = tm + ty * TM + i;
        float bv = HASBIAS ? bias[row] : 0.f;
        #pragma unroll
        for (int j = 0; j < TN; j += 4) {
            float4 v;
            v.x = acc[i][j + 0] + bv;
            v.y = acc[i][j + 1] + bv;
            v.z = acc[i][j + 2] + bv;
            v.w = acc[i][j + 3] + bv;
            *reinterpret_cast<float4*>(
                &Cp[(size_t)row * N + tn + tx * TN + j]) = v;
        }
    }
}

// softmax over last dim (C_=512) of S[B*C, C], with pre-scale
__global__ void softmax_kernel(float* __restrict__ S, float scale)
{
    int warp = (blockIdx.x * blockDim.x + threadIdx.x) >> 5;
    int lane = threadIdx.x & 31;
    if (warp >= B_ * C_) return;
    float* row = S + (size_t)warp * C_;

    float vals[C_ / 32];
    float m = -1e30f;
    #pragma unroll
    for (int t = 0; t < C_ / 32; t++) {
        vals[t] = row[lane + t * 32] * scale;
        m = fmaxf(m, vals[t]);
    }
    #pragma unroll
    for (int o = 16; o; o >>= 1) m = fmaxf(m, __shfl_xor_sync(0xffffffffu, m, o));

    float s = 0.f;
    #pragma unroll
    for (int t = 0; t < C_ / 32; t++) {
        vals[t] = __expf(vals[t] - m);
        s += vals[t];
    }
    #pragma unroll
    for (int o = 16; o; o >>= 1) s += __shfl_xor_sync(0xffffffffu, s, o);

    float inv = 1.f / s;
    #pragma unroll
    for (int t = 0; t < C_ / 32; t++) row[lane + t * 32] = vals[t] * inv;
}

extern "C" void kernel_launch(void* const* d_in, const int* in_sizes, int n_in,
                              void* d_out, int out_size)
{
    const float* x      = (const float*)d_in[0];
    const float* w_qkv  = (const float*)d_in[1];
    const float* b_qkv  = (const float*)d_in[2];
    const float* w_proj = (const float*)d_in[3];
    const float* b_proj = (const float*)d_in[4];
    float* out = (float*)d_out;

    float* qkv  = nullptr;
    float* attn = nullptr;
    cudaGetSymbolAddress((void**)&qkv,  g_qkv);
    cudaGetSymbolAddress((void**)&attn, g_attn);

    const float scale = 1.0f / sqrtf((float)C_);
    dim3 blk(256);

    // 1) qkv[b,o,n] = sum_c w_qkv[o,c] * x[b,c,n] + b_qkv[o]
    gemm_kernel<false, true><<<dim3(N_ / BN, O3 / BM, B_), blk>>>(
        w_qkv, x, qkv, b_qkv,
        O3, N_, C_,
        0, (size_t)C_ * N_, (size_t)O3 * N_);

    // 2) S[b,c,d] = sum_n q[b,c,n] * k[b,d,n]   (q = qkv rows 0..C, k = rows C..2C)
    gemm_kernel<true, false><<<dim3(C_ / BN, C_ / BM, B_), blk>>>(
        qkv, qkv + (size_t)C_ * N_, attn, nullptr,
        C_, C_, N_,
        (size_t)O3 * N_, (size_t)O3 * N_, (size_t)C_ * C_);

    // 3) softmax over d with scale
    {
        int rows = B_ * C_;                 // 4096 warps
        int blocks = (rows * 32 + 255) / 256;
        softmax_kernel<<<blocks, 256>>>(attn, scale);
    }

    // 4) o1[b,c,n] = sum_d attn[b,c,d] * v[b,d,n]   (writes over dead q region)
    gemm_kernel<false, false><<<dim3(N_ / BN, C_ / BM, B_), blk>>>(
        attn, qkv + (size_t)(2 * C_) * N_, qkv, nullptr,
        C_, N_, C_,
        (size_t)C_ * C_, (size_t)O3 * N_, (size_t)O3 * N_);

    // 5) out[b,o,n] = sum_c w_proj[o,c] * o1[b,c,n] + b_proj[o]
    gemm_kernel<false, true><<<dim3(N_ / BN, C_ / BM, B_), blk>>>(
        w_proj, qkv, out, b_proj,
        C_, N_, C_,
        0, (size_t)O3 * N_, (size_t)C_ * N_);
}

// round 4
// speedup vs baseline: 1.8989x; 1.8989x over previous
#include <cuda_runtime.h>
#include <cuda_bf16.h>
#include <math.h>
#include <stdint.h>

// ---------------- problem constants ----------------
constexpr int B_ = 8, C_ = 512, H_ = 96, W_ = 96;
constexpr int N_ = H_ * W_;    // 9216
constexpr int O3 = 3 * C_;     // 1536

// ---------------- scratch: bf16 hi/lo planes ----------------
__device__ __align__(256) __nv_bfloat16 g_qh [(size_t)B_ * O3 * N_];
__device__ __align__(256) __nv_bfloat16 g_ql [(size_t)B_ * O3 * N_];
__device__ __align__(256) __nv_bfloat16 g_xTh[(size_t)B_ * N_ * C_];  // reused as o1T
__device__ __align__(256) __nv_bfloat16 g_xTl[(size_t)B_ * N_ * C_];
__device__ __align__(256) __nv_bfloat16 g_vTh[(size_t)B_ * N_ * C_];
__device__ __align__(256) __nv_bfloat16 g_vTl[(size_t)B_ * N_ * C_];
__device__ __align__(256) float         g_S  [(size_t)B_ * C_ * C_];
__device__ __align__(256) __nv_bfloat16 g_ah [(size_t)B_ * C_ * C_];
__device__ __align__(256) __nv_bfloat16 g_al [(size_t)B_ * C_ * C_];
__device__ __align__(256) __nv_bfloat16 g_wqh[(size_t)O3 * C_];
__device__ __align__(256) __nv_bfloat16 g_wql[(size_t)O3 * C_];
__device__ __align__(256) __nv_bfloat16 g_wph[(size_t)C_ * C_];
__device__ __align__(256) __nv_bfloat16 g_wpl[(size_t)C_ * C_];

// ---------------- GEMM config ----------------
#define BM 128
#define BN 128
#define BK 32
#define LDT 40                      // smem row stride in bf16 (BK + 8 pad)
#define TILE_BYTES (128 * LDT * 2)  // 10240
#define TILE_ELEMS (128 * LDT)      // 5120
#define STAGE_BYTES (4 * TILE_BYTES)
#define NSTAGE 3
#define SMEM_BYTES (NSTAGE * STAGE_BYTES)   // 122880

__device__ __forceinline__ uint32_t smem_u32(const void* p) {
    uint32_t a;
    asm("{ .reg .u64 t; cvta.to.shared.u64 t, %1; cvt.u32.u64 %0, t; }"
        : "=r"(a) : "l"(p));
    return a;
}
__device__ __forceinline__ void cp16(uint32_t dst, const void* src) {
    asm volatile("cp.async.cg.shared.global [%0], [%1], 16;"
                 :: "r"(dst), "l"(src));
}
__device__ __forceinline__ void mma16816(float* d, const uint32_t* a,
                                         const uint32_t* b) {
    asm volatile(
        "mma.sync.aligned.m16n8k16.row.col.f32.bf16.bf16.f32 "
        "{%0,%1,%2,%3}, {%4,%5,%6,%7}, {%8,%9}, {%0,%1,%2,%3};"
        : "+f"(d[0]), "+f"(d[1]), "+f"(d[2]), "+f"(d[3])
        : "r"(a[0]), "r"(a[1]), "r"(a[2]), "r"(a[3]), "r"(b[0]), "r"(b[1]));
}
__device__ __forceinline__ uint32_t ld32s(const __nv_bfloat16* p) {
    return *reinterpret_cast<const uint32_t*>(p);
}
__device__ __forceinline__ uint32_t pack2(__nv_bfloat16 a, __nv_bfloat16 b) {
    return (uint32_t)__bfloat16_as_ushort(a) |
           ((uint32_t)__bfloat16_as_ushort(b) << 16);
}

// D[m,j] = sum_k A[m,k]*B[j,k], A/B given as bf16 hi+lo planes (3-pass compensated)
template<bool HASBIAS, bool SPLITOUT>
__global__ __launch_bounds__(256)
void gemm_mma(const __nv_bfloat16* __restrict__ Ah, const __nv_bfloat16* __restrict__ Al,
              const __nv_bfloat16* __restrict__ Bh, const __nv_bfloat16* __restrict__ Bl,
              float* __restrict__ Cf,
              __nv_bfloat16* __restrict__ Ch, __nv_bfloat16* __restrict__ Cl,
              const float* __restrict__ bias,
              int K, int lda, int ldb, int ldc,
              size_t sA_, size_t sB_, size_t sC_)
{
    extern __shared__ __nv_bfloat16 smem[];
    const int tid  = threadIdx.x;
    const int warp = tid >> 5;
    const int lane = tid & 31;
    const int wm   = (warp >> 2) * 64;   // warp M origin within CTA
    const int wn   = (warp & 3) * 32;    // warp N origin within CTA
    const int tm   = blockIdx.y * BM;
    const int tn   = blockIdx.x * BN;

    const __nv_bfloat16* Ahb = Ah + (size_t)blockIdx.z * sA_;
    const __nv_bfloat16* Alb = Al + (size_t)blockIdx.z * sA_;
    const __nv_bfloat16* Bhb = Bh + (size_t)blockIdx.z * sB_;
    const __nv_bfloat16* Blb = Bl + (size_t)blockIdx.z * sB_;

    // per-thread cp.async assignment: row = tid>>1, two 16B granules
    const int lrow = tid >> 1;
    const int lg   = (tid & 1) * 2;           // granule 0 or 2
    const __nv_bfloat16* pAh = Ahb + (size_t)(tm + lrow) * lda + lg * 8;
    const __nv_bfloat16* pAl = Alb + (size_t)(tm + lrow) * lda + lg * 8;
    const __nv_bfloat16* pBh = Bhb + (size_t)(tn + lrow) * ldb + lg * 8;
    const __nv_bfloat16* pBl = Blb + (size_t)(tn + lrow) * ldb + lg * 8;
    const uint32_t sbase = smem_u32(smem);
    const uint32_t doff  = lrow * (LDT * 2) + lg * 16;

    float acc[4][4][4];
    #pragma unroll
    for (int i = 0; i < 4; i++)
        #pragma unroll
        for (int j = 0; j < 4; j++)
            #pragma unroll
            for (int t = 0; t < 4; t++) acc[i][j][t] = 0.f;

    auto issue = [&](int c, int st) {
        const uint32_t sb = sbase + st * STAGE_BYTES + doff;
        const int k0 = c * BK;
        cp16(sb + 0 * TILE_BYTES,      pAh + k0);
        cp16(sb + 0 * TILE_BYTES + 16, pAh + k0 + 8);
        cp16(sb + 1 * TILE_BYTES,      pAl + k0);
        cp16(sb + 1 * TILE_BYTES + 16, pAl + k0 + 8);
        cp16(sb + 2 * TILE_BYTES,      pBh + k0);
        cp16(sb + 2 * TILE_BYTES + 16, pBh + k0 + 8);
        cp16(sb + 3 * TILE_BYTES,      pBl + k0);
        cp16(sb + 3 * TILE_BYTES + 16, pBl + k0 + 8);
    };

    const int nc = K / BK;
    issue(0, 0);
    asm volatile("cp.async.commit_group;");
    if (nc > 1) issue(1, 1);
    asm volatile("cp.async.commit_group;");

    const int arow = wm + (lane >> 2);
    const int brow = wn + (lane >> 2);
    const int kcol = (lane & 3) * 2;

    for (int c = 0; c < nc; ++c) {
        __syncthreads();                 // all warps done with stage being refilled
        if (c + 2 < nc) issue(c + 2, (c + 2) % NSTAGE);
        asm volatile("cp.async.commit_group;");
        asm volatile("cp.async.wait_group 2;");
        __syncthreads();                 // loaded data visible to all warps

        const __nv_bfloat16* st  = smem + (c % NSTAGE) * (STAGE_BYTES / 2);
        const __nv_bfloat16* sAh = st;
        const __nv_bfloat16* sAl = st + TILE_ELEMS;
        const __nv_bfloat16* sBh = st + 2 * TILE_ELEMS;
        const __nv_bfloat16* sBl = st + 3 * TILE_ELEMS;

        #pragma unroll
        for (int ks = 0; ks < 2; ++ks) {
            const int kk = ks * 16 + kcol;
            uint32_t ah[4][4], al_[4][4], bh[4][2], bl_[4][2];
            #pragma unroll
            for (int i = 0; i < 4; i++) {
                int base = (arow + i * 16) * LDT + kk;
                ah[i][0]  = ld32s(sAh + base);
                ah[i][1]  = ld32s(sAh + base + 8 * LDT);
                ah[i][2]  = ld32s(sAh + base + 8);
                ah[i][3]  = ld32s(sAh + base + 8 * LDT + 8);
                al_[i][0] = ld32s(sAl + base);
                al_[i][1] = ld32s(sAl + base + 8 * LDT);
                al_[i][2] = ld32s(sAl + base + 8);
                al_[i][3] = ld32s(sAl + base + 8 * LDT + 8);
            }
            #pragma unroll
            for (int j = 0; j < 4; j++) {
                int base = (brow + j * 8) * LDT + kk;
                bh[j][0]  = ld32s(sBh + base);
                bh[j][1]  = ld32s(sBh + base + 8);
                bl_[j][0] = ld32s(sBl + base);
                bl_[j][1] = ld32s(sBl + base + 8);
            }
            #pragma unroll
            for (int i = 0; i < 4; i++)
                #pragma unroll
                for (int j = 0; j < 4; j++) {
                    mma16816(acc[i][j], ah[i],  bh[j]);
                    mma16816(acc[i][j], al_[i], bh[j]);
                    mma16816(acc[i][j], ah[i],  bl_[j]);
                }
        }
    }

    // ---------------- epilogue ----------------
    #pragma unroll
    for (int i = 0; i < 4; i++) {
        const int r0 = tm + wm + i * 16 + (lane >> 2);
        float bv0 = 0.f, bv1 = 0.f;
        if (HASBIAS) { bv0 = bias[r0]; bv1 = bias[r0 + 8]; }
        #pragma unroll
        for (int j = 0; j < 4; j++) {
            const int cc = tn + wn + j * 8 + (lane & 3) * 2;
            float d0 = acc[i][j][0] + bv0, d1 = acc[i][j][1] + bv0;
            float d2 = acc[i][j][2] + bv1, d3 = acc[i][j][3] + bv1;
            if (SPLITOUT) {
                __nv_bfloat16* chp = Ch + (size_t)blockIdx.z * sC_;
                __nv_bfloat16* clp = Cl + (size_t)blockIdx.z * sC_;
                __nv_bfloat16 h0 = __float2bfloat16(d0), h1 = __float2bfloat16(d1);
                __nv_bfloat16 h2 = __float2bfloat16(d2), h3 = __float2bfloat16(d3);
                __nv_bfloat16 l0 = __float2bfloat16(d0 - __bfloat162float(h0));
                __nv_bfloat16 l1 = __float2bfloat16(d1 - __bfloat162float(h1));
                __nv_bfloat16 l2 = __float2bfloat16(d2 - __bfloat162float(h2));
                __nv_bfloat16 l3 = __float2bfloat16(d3 - __bfloat162float(h3));
                *reinterpret_cast<uint32_t*>(&chp[(size_t)r0 * ldc + cc])       = pack2(h0, h1);
                *reinterpret_cast<uint32_t*>(&clp[(size_t)r0 * ldc + cc])       = pack2(l0, l1);
                *reinterpret_cast<uint32_t*>(&chp[(size_t)(r0 + 8) * ldc + cc]) = pack2(h2, h3);
                *reinterpret_cast<uint32_t*>(&clp[(size_t)(r0 + 8) * ldc + cc]) = pack2(l2, l3);
            } else {
                float* cfp = Cf + (size_t)blockIdx.z * sC_;
                *reinterpret_cast<float2*>(&cfp[(size_t)r0 * ldc + cc])       = make_float2(d0, d1);
                *reinterpret_cast<float2*>(&cfp[(size_t)(r0 + 8) * ldc + cc]) = make_float2(d2, d3);
            }
        }
    }
}

// ---------------- transpose + split: fp32 [R,Cc] -> bf16 hi/lo [Cc,R] ------
__global__ void transpose_split(const float* __restrict__ in,
                                __nv_bfloat16* __restrict__ oh,
                                __nv_bfloat16* __restrict__ ol,
                                int R, int Cc, size_t sIn, size_t sOut)
{
    __shared__ float t[32][33];
    const float* ip = in + (size_t)blockIdx.z * sIn;
    int r0 = blockIdx.y * 32, c0 = blockIdx.x * 32;
    #pragma unroll
    for (int j = threadIdx.y; j < 32; j += 8)
        t[j][threadIdx.x] = ip[(size_t)(r0 + j) * Cc + c0 + threadIdx.x];
    __syncthreads();
    #pragma unroll
    for (int j = threadIdx.y; j < 32; j += 8) {
        float f = t[threadIdx.x][j];
        __nv_bfloat16 h = __float2bfloat16(f);
        __nv_bfloat16 l = __float2bfloat16(f - __bfloat162float(h));
        size_t idx = (size_t)blockIdx.z * sOut + (size_t)(c0 + j) * R + r0 + threadIdx.x;
        oh[idx] = h;
        ol[idx] = l;
    }
}

// ---------------- transpose two bf16 planes: [R,Cc] -> [Cc,R] --------------
__global__ void transpose_b2(const __nv_bfloat16* __restrict__ ih,
                             const __nv_bfloat16* __restrict__ il,
                             __nv_bfloat16* __restrict__ oh,
                             __nv_bfloat16* __restrict__ ol,
                             int R, int Cc, size_t sIn, size_t sOut)
{
    __shared__ __nv_bfloat16 th[32][34], tl[32][34];
    const __nv_bfloat16* ihp = ih + (size_t)blockIdx.z * sIn;
    const __nv_bfloat16* ilp = il + (size_t)blockIdx.z * sIn;
    int r0 = blockIdx.y * 32, c0 = blockIdx.x * 32;
    #pragma unroll
    for (int j = threadIdx.y; j < 32; j += 8) {
        size_t s = (size_t)(r0 + j) * Cc + c0 + threadIdx.x;
        th[j][threadIdx.x] = ihp[s];
        tl[j][threadIdx.x] = ilp[s];
    }
    __syncthreads();
    #pragma unroll
    for (int j = threadIdx.y; j < 32; j += 8) {
        size_t d = (size_t)blockIdx.z * sOut + (size_t)(c0 + j) * R + r0 + threadIdx.x;
        oh[d] = th[threadIdx.x][j];
        ol[d] = tl[threadIdx.x][j];
    }
}

// ---------------- elementwise split fp32 -> bf16 hi/lo ---------------------
__global__ void split_w(const float* __restrict__ in,
                        __nv_bfloat16* __restrict__ oh,
                        __nv_bfloat16* __restrict__ ol, int n)
{
    int i = blockIdx.x * blockDim.x + threadIdx.x;
    if (i >= n) return;
    float f = in[i];
    __nv_bfloat16 h = __float2bfloat16(f);
    oh[i] = h;
    ol[i] = __float2bfloat16(f - __bfloat162float(h));
}

// ---------------- softmax (fp32 in, bf16 hi/lo out), rows of 512 -----------
__global__ void softmax_split(const float* __restrict__ S,
                              __nv_bfloat16* __restrict__ oh,
                              __nv_bfloat16* __restrict__ ol, float scale)
{
    int warp = (blockIdx.x * blockDim.x + threadIdx.x) >> 5;
    int lane = threadIdx.x & 31;
    if (warp >= B_ * C_) return;
    const float* row = S + (size_t)warp * C_;

    float vals[C_ / 32];
    float m = -1e30f;
    #pragma unroll
    for (int t = 0; t < C_ / 32; t++) {
        vals[t] = row[lane + t * 32] * scale;
        m = fmaxf(m, vals[t]);
    }
    #pragma unroll
    for (int o = 16; o; o >>= 1) m = fmaxf(m, __shfl_xor_sync(0xffffffffu, m, o));
    float s = 0.f;
    #pragma unroll
    for (int t = 0; t < C_ / 32; t++) { vals[t] = __expf(vals[t] - m); s += vals[t]; }
    #pragma unroll
    for (int o = 16; o; o >>= 1) s += __shfl_xor_sync(0xffffffffu, s, o);
    float inv = 1.f / s;
    #pragma unroll
    for (int t = 0; t < C_ / 32; t++) {
        float p = vals[t] * inv;
        __nv_bfloat16 h = __float2bfloat16(p);
        size_t idx = (size_t)warp * C_ + lane + t * 32;
        oh[idx] = h;
        ol[idx] = __float2bfloat16(p - __bfloat162float(h));
    }
}

// ---------------- launcher ----------------
extern "C" void kernel_launch(void* const* d_in, const int* in_sizes, int n_in,
                              void* d_out, int out_size)
{
    const float* x      = (const float*)d_in[0];
    const float* w_qkv  = (const float*)d_in[1];
    const float* b_qkv  = (const float*)d_in[2];
    const float* w_proj = (const float*)d_in[3];
    const float* b_proj = (const float*)d_in[4];
    float* out = (float*)d_out;

    __nv_bfloat16 *qh, *ql, *xTh, *xTl, *vTh, *vTl, *ah, *al, *wqh, *wql, *wph, *wpl;
    float *S;
    cudaGetSymbolAddress((void**)&qh,  g_qh);
    cudaGetSymbolAddress((void**)&ql,  g_ql);
    cudaGetSymbolAddress((void**)&xTh, g_xTh);
    cudaGetSymbolAddress((void**)&xTl, g_xTl);
    cudaGetSymbolAddress((void**)&vTh, g_vTh);
    cudaGetSymbolAddress((void**)&vTl, g_vTl);
    cudaGetSymbolAddress((void**)&S,   g_S);
    cudaGetSymbolAddress((void**)&ah,  g_ah);
    cudaGetSymbolAddress((void**)&al,  g_al);
    cudaGetSymbolAddress((void**)&wqh, g_wqh);
    cudaGetSymbolAddress((void**)&wql, g_wql);
    cudaGetSymbolAddress((void**)&wph, g_wph);
    cudaGetSymbolAddress((void**)&wpl, g_wpl);

    cudaFuncSetAttribute(gemm_mma<true,  true>,  cudaFuncAttributeMaxDynamicSharedMemorySize, SMEM_BYTES);
    cudaFuncSetAttribute(gemm_mma<false, false>, cudaFuncAttributeMaxDynamicSharedMemorySize, SMEM_BYTES);
    cudaFuncSetAttribute(gemm_mma<false, true>,  cudaFuncAttributeMaxDynamicSharedMemorySize, SMEM_BYTES);
    cudaFuncSetAttribute(gemm_mma<true,  false>, cudaFuncAttributeMaxDynamicSharedMemorySize, SMEM_BYTES);

    const float scale = 1.0f / sqrtf((float)C_);
    dim3 tblk(32, 8);

    // 0) split weights
    split_w<<<(O3 * C_ + 255) / 256, 256>>>(w_qkv, wqh, wql, O3 * C_);
    split_w<<<(C_ * C_ + 255) / 256, 256>>>(w_proj, wph, wpl, C_ * C_);

    // 1) xT hi/lo: x[b,c,n] -> [b,n,c]
    transpose_split<<<dim3(N_ / 32, C_ / 32, B_), tblk>>>(
        x, xTh, xTl, C_, N_, (size_t)C_ * N_, (size_t)N_ * C_);

    // 2) qkv = w_qkv @ xT^T + b  -> bf16 hi/lo [b,1536,9216]
    gemm_mma<true, true><<<dim3(N_ / BN, O3 / BM, B_), 256, SMEM_BYTES>>>(
        wqh, wql, xTh, xTl, nullptr, qh, ql, b_qkv,
        C_, C_, C_, N_,
        0, (size_t)N_ * C_, (size_t)O3 * N_);

    // 3) vT hi/lo: v[b,d,n] -> [b,n,d]
    transpose_b2<<<dim3(N_ / 32, C_ / 32, B_), tblk>>>(
        qh + (size_t)2 * C_ * N_, ql + (size_t)2 * C_ * N_, vTh, vTl,
        C_, N_, (size_t)O3 * N_, (size_t)N_ * C_);

    // 4) S = q @ k^T (fp32)
    gemm_mma<false, false><<<dim3(C_ / BN, C_ / BM, B_), 256, SMEM_BYTES>>>(
        qh, ql, qh + (size_t)C_ * N_, ql + (size_t)C_ * N_,
        S, nullptr, nullptr, nullptr,
        N_, N_, N_, C_,
        (size_t)O3 * N_, (size_t)O3 * N_, (size_t)C_ * C_);

    // 5) softmax -> attn hi/lo
    softmax_split<<<(B_ * C_ * 32 + 255) / 256, 256>>>(S, ah, al, scale);

    // 6) o1T[b,n,c] = vT[b,n,:] @ attn[b,c,:]  -> bf16 hi/lo (reuse xT buffers)
    gemm_mma<false, true><<<dim3(C_ / BN, N_ / BM, B_), 256, SMEM_BYTES>>>(
        vTh, vTl, ah, al, nullptr, xTh, xTl, nullptr,
        C_, C_, C_, C_,
        (size_t)N_ * C_, (size_t)C_ * C_, (size_t)N_ * C_);

    // 7) out = w_proj @ o1T^T + b (fp32)
    gemm_mma<true, false><<<dim3(N_ / BN, C_ / BM, B_), 256, SMEM_BYTES>>>(
        wph, wpl, xTh, xTl, out, nullptr, nullptr, b_proj,
        C_, C_, C_, N_,
        0, (size_t)N_ * C_, (size_t)C_ * N_);
}

// round 5
// speedup vs baseline: 2.1894x; 1.1530x over previous
#include <cuda_runtime.h>
#include <cuda_bf16.h>
#include <math.h>
#include <stdint.h>

// ---------------- problem constants ----------------
constexpr int B_ = 8, C_ = 512, H_ = 96, W_ = 96;
constexpr int N_ = H_ * W_;    // 9216
constexpr int O3 = 3 * C_;     // 1536

// ---------------- scratch: bf16 hi/lo planes ----------------
__device__ __align__(256) __nv_bfloat16 g_qh [(size_t)B_ * O3 * N_];
__device__ __align__(256) __nv_bfloat16 g_ql [(size_t)B_ * O3 * N_];
__device__ __align__(256) __nv_bfloat16 g_xTh[(size_t)B_ * N_ * C_];  // reused as o1T
__device__ __align__(256) __nv_bfloat16 g_xTl[(size_t)B_ * N_ * C_];
__device__ __align__(256) __nv_bfloat16 g_vTh[(size_t)B_ * N_ * C_];
__device__ __align__(256) __nv_bfloat16 g_vTl[(size_t)B_ * N_ * C_];
__device__ __align__(256) float         g_S  [(size_t)B_ * C_ * C_];
__device__ __align__(256) __nv_bfloat16 g_ah [(size_t)B_ * C_ * C_];
__device__ __align__(256) __nv_bfloat16 g_al [(size_t)B_ * C_ * C_];
__device__ __align__(256) __nv_bfloat16 g_wqh[(size_t)O3 * C_];
__device__ __align__(256) __nv_bfloat16 g_wql[(size_t)O3 * C_];
__device__ __align__(256) __nv_bfloat16 g_wph[(size_t)C_ * C_];
__device__ __align__(256) __nv_bfloat16 g_wpl[(size_t)C_ * C_];

// ---------------- common helpers ----------------
#define BK 32
#define LDT 40   // smem row stride in bf16 (BK + 8 pad)

__device__ __forceinline__ uint32_t smem_u32(const void* p) {
    uint32_t a;
    asm("{ .reg .u64 t; cvta.to.shared.u64 t, %1; cvt.u32.u64 %0, t; }"
        : "=r"(a) : "l"(p));
    return a;
}
__device__ __forceinline__ void cp16(uint32_t dst, const void* src) {
    asm volatile("cp.async.cg.shared.global [%0], [%1], 16;"
                 :: "r"(dst), "l"(src));
}
__device__ __forceinline__ void mma16816(float* d, const uint32_t* a,
                                         const uint32_t* b) {
    asm volatile(
        "mma.sync.aligned.m16n8k16.row.col.f32.bf16.bf16.f32 "
        "{%0,%1,%2,%3}, {%4,%5,%6,%7}, {%8,%9}, {%0,%1,%2,%3};"
        : "+f"(d[0]), "+f"(d[1]), "+f"(d[2]), "+f"(d[3])
        : "r"(a[0]), "r"(a[1]), "r"(a[2]), "r"(a[3]), "r"(b[0]), "r"(b[1]));
}
__device__ __forceinline__ uint32_t ld32s(const __nv_bfloat16* p) {
    return *reinterpret_cast<const uint32_t*>(p);
}
__device__ __forceinline__ uint32_t pack2(__nv_bfloat16 a, __nv_bfloat16 b) {
    return (uint32_t)__bfloat16_as_ushort(a) |
           ((uint32_t)__bfloat16_as_ushort(b) << 16);
}

// ================= BIG kernel: 128(M) x 256(N), 512 threads, 3-stage ======
#define BM2 128
#define BN2 256
#define NST2 3
// plane elem offsets within a stage (bf16 elems)
#define P_AH 0
#define P_AL (128 * LDT)
#define P_BH (256 * LDT)
#define P_BL (512 * LDT)
#define STAGE_EL2 (768 * LDT)                 // 30720 elems
#define STAGE_BY2 (STAGE_EL2 * 2)             // 61440 B
#define SMEM_BY2 (NST2 * STAGE_BY2)           // 184320 B

template<bool HASBIAS, bool SPLITOUT>
__global__ __launch_bounds__(512)
void gemm_big(const __nv_bfloat16* __restrict__ Ah, const __nv_bfloat16* __restrict__ Al,
              const __nv_bfloat16* __restrict__ Bh, const __nv_bfloat16* __restrict__ Bl,
              float* __restrict__ Cf,
              __nv_bfloat16* __restrict__ Ch, __nv_bfloat16* __restrict__ Cl,
              const float* __restrict__ bias,
              int K, int lda, int ldb, int ldc,
              size_t sA_, size_t sB_, size_t sC_)
{
    extern __shared__ __nv_bfloat16 smem[];
    const int tid  = threadIdx.x;
    const int warp = tid >> 5;
    const int lane = tid & 31;
    const int wm   = (warp >> 3) * 64;   // 2 warps in M
    const int wn   = (warp & 7) * 32;    // 8 warps in N
    const int tm   = blockIdx.y * BM2;
    const int tn   = blockIdx.x * BN2;

    const __nv_bfloat16* Ahb = Ah + (size_t)blockIdx.z * sA_;
    const __nv_bfloat16* Alb = Al + (size_t)blockIdx.z * sA_;
    const __nv_bfloat16* Bhb = Bh + (size_t)blockIdx.z * sB_;
    const __nv_bfloat16* Blb = Bl + (size_t)blockIdx.z * sB_;

    // cp.async mapping: A planes 128 rows x 4 granules = 512 (one per thread)
    //                   B planes 256 rows x 4 granules = 1024 (two per thread)
    const int arow0 = tid >> 2, ag0 = (tid & 3) * 8;
    const int b1    = tid,      b2  = tid + 512;
    const int brow1 = b1 >> 2,  bg1 = (b1 & 3) * 8;
    const int brow2 = b2 >> 2,  bg2 = (b2 & 3) * 8;

    const __nv_bfloat16* pAh = Ahb + (size_t)(tm + arow0) * lda + ag0;
    const __nv_bfloat16* pAl = Alb + (size_t)(tm + arow0) * lda + ag0;
    const __nv_bfloat16* pB1h = Bhb + (size_t)(tn + brow1) * ldb + bg1;
    const __nv_bfloat16* pB1l = Blb + (size_t)(tn + brow1) * ldb + bg1;
    const __nv_bfloat16* pB2h = Bhb + (size_t)(tn + brow2) * ldb + bg2;
    const __nv_bfloat16* pB2l = Blb + (size_t)(tn + brow2) * ldb + bg2;

    const uint32_t sbase = smem_u32(smem);
    const uint32_t dA  = (arow0 * LDT + ag0) * 2;
    const uint32_t dB1 = (brow1 * LDT + bg1) * 2;
    const uint32_t dB2 = (brow2 * LDT + bg2) * 2;

    float acc[4][4][4];
    #pragma unroll
    for (int i = 0; i < 4; i++)
        #pragma unroll
        for (int j = 0; j < 4; j++)
            #pragma unroll
            for (int t = 0; t < 4; t++) acc[i][j][t] = 0.f;

    auto issue = [&](int c) {
        const int st = c % NST2;
        const uint32_t sb = sbase + st * STAGE_BY2;
        const int k0 = c * BK;
        cp16(sb + P_AH * 2 + dA,  pAh + k0);
        cp16(sb + P_AL * 2 + dA,  pAl + k0);
        cp16(sb + P_BH * 2 + dB1, pB1h + k0);
        cp16(sb + P_BL * 2 + dB1, pB1l + k0);
        cp16(sb + P_BH * 2 + dB2, pB2h + k0);
        cp16(sb + P_BL * 2 + dB2, pB2l + k0);
    };

    const int nc = K / BK;
    issue(0);
    asm volatile("cp.async.commit_group;");
    issue(1);
    asm volatile("cp.async.commit_group;");

    const int arow = wm + (lane >> 2);
    const int brow = wn + (lane >> 2);
    const int kcol = (lane & 3) * 2;

    for (int c = 0; c < nc; ++c) {
        asm volatile("cp.async.wait_group 1;");
        __syncthreads();
        if (c + 2 < nc) issue(c + 2);
        asm volatile("cp.async.commit_group;");

        const __nv_bfloat16* st  = smem + (c % NST2) * STAGE_EL2;
        const __nv_bfloat16* sAh = st + P_AH;
        const __nv_bfloat16* sAl = st + P_AL;
        const __nv_bfloat16* sBh = st + P_BH;
        const __nv_bfloat16* sBl = st + P_BL;

        #pragma unroll
        for (int ks = 0; ks < 2; ++ks) {
            const int kk = ks * 16 + kcol;
            uint32_t ah[4][4], al_[4][4];
            #pragma unroll
            for (int i = 0; i < 4; i++) {
                int base = (arow + i * 16) * LDT + kk;
                ah[i][0]  = ld32s(sAh + base);
                ah[i][1]  = ld32s(sAh + base + 8 * LDT);
                ah[i][2]  = ld32s(sAh + base + 8);
                ah[i][3]  = ld32s(sAh + base + 8 * LDT + 8);
                al_[i][0] = ld32s(sAl + base);
                al_[i][1] = ld32s(sAl + base + 8 * LDT);
                al_[i][2] = ld32s(sAl + base + 8);
                al_[i][3] = ld32s(sAl + base + 8 * LDT + 8);
            }
            #pragma unroll
            for (int j = 0; j < 4; j++) {
                int base = (brow + j * 8) * LDT + kk;
                uint32_t bh[2], bl_[2];
                bh[0]  = ld32s(sBh + base);
                bh[1]  = ld32s(sBh + base + 8);
                bl_[0] = ld32s(sBl + base);
                bl_[1] = ld32s(sBl + base + 8);
                #pragma unroll
                for (int i = 0; i < 4; i++) {
                    mma16816(acc[i][j], ah[i],  bh);
                    mma16816(acc[i][j], al_[i], bh);
                    mma16816(acc[i][j], ah[i],  bl_);
                }
            }
        }
    }

    // ---------------- epilogue ----------------
    #pragma unroll
    for (int i = 0; i < 4; i++) {
        const int r0 = tm + wm + i * 16 + (lane >> 2);
        float bv0 = 0.f, bv1 = 0.f;
        if (HASBIAS) { bv0 = bias[r0]; bv1 = bias[r0 + 8]; }
        #pragma unroll
        for (int j = 0; j < 4; j++) {
            const int cc = tn + wn + j * 8 + (lane & 3) * 2;
            float d0 = acc[i][j][0] + bv0, d1 = acc[i][j][1] + bv0;
            float d2 = acc[i][j][2] + bv1, d3 = acc[i][j][3] + bv1;
            if (SPLITOUT) {
                __nv_bfloat16* chp = Ch + (size_t)blockIdx.z * sC_;
                __nv_bfloat16* clp = Cl + (size_t)blockIdx.z * sC_;
                __nv_bfloat16 h0 = __float2bfloat16(d0), h1 = __float2bfloat16(d1);
                __nv_bfloat16 h2 = __float2bfloat16(d2), h3 = __float2bfloat16(d3);
                __nv_bfloat16 l0 = __float2bfloat16(d0 - __bfloat162float(h0));
                __nv_bfloat16 l1 = __float2bfloat16(d1 - __bfloat162float(h1));
                __nv_bfloat16 l2 = __float2bfloat16(d2 - __bfloat162float(h2));
                __nv_bfloat16 l3 = __float2bfloat16(d3 - __bfloat162float(h3));
                *reinterpret_cast<uint32_t*>(&chp[(size_t)r0 * ldc + cc])       = pack2(h0, h1);
                *reinterpret_cast<uint32_t*>(&clp[(size_t)r0 * ldc + cc])       = pack2(l0, l1);
                *reinterpret_cast<uint32_t*>(&chp[(size_t)(r0 + 8) * ldc + cc]) = pack2(h2, h3);
                *reinterpret_cast<uint32_t*>(&clp[(size_t)(r0 + 8) * ldc + cc]) = pack2(l2, l3);
            } else {
                float* cfp = Cf + (size_t)blockIdx.z * sC_;
                *reinterpret_cast<float2*>(&cfp[(size_t)r0 * ldc + cc])       = make_float2(d0, d1);
                *reinterpret_cast<float2*>(&cfp[(size_t)(r0 + 8) * ldc + cc]) = make_float2(d2, d3);
            }
        }
    }
}

// ================= S kernel: 128x128, 256 threads, 2-stage (2 CTA/SM) =====
#define SP_AH 0
#define SP_AL (128 * LDT)
#define SP_BH (256 * LDT)
#define SP_BL (384 * LDT)
#define STAGE_ELS (512 * LDT)                 // 20480 elems
#define STAGE_BYS (STAGE_ELS * 2)             // 40960 B
#define NSTS 2
#define SMEM_BYS (NSTS * STAGE_BYS)           // 81920 B

__global__ __launch_bounds__(256)
void gemm_s(const __nv_bfloat16* __restrict__ Ah, const __nv_bfloat16* __restrict__ Al,
            const __nv_bfloat16* __restrict__ Bh, const __nv_bfloat16* __restrict__ Bl,
            float* __restrict__ Cf,
            int K, int lda, int ldb, int ldc,
            size_t sA_, size_t sB_, size_t sC_)
{
    extern __shared__ __nv_bfloat16 smem[];
    const int tid  = threadIdx.x;
    const int warp = tid >> 5;
    const int lane = tid & 31;
    const int wm   = (warp >> 2) * 64;
    const int wn   = (warp & 3) * 32;
    const int tm   = blockIdx.y * 128;
    const int tn   = blockIdx.x * 128;

    const __nv_bfloat16* Ahb = Ah + (size_t)blockIdx.z * sA_;
    const __nv_bfloat16* Alb = Al + (size_t)blockIdx.z * sA_;
    const __nv_bfloat16* Bhb = Bh + (size_t)blockIdx.z * sB_;
    const __nv_bfloat16* Blb = Bl + (size_t)blockIdx.z * sB_;

    const int lrow = tid >> 1;
    const int lg   = (tid & 1) * 16;  // bf16 offset of first granule pair
    const __nv_bfloat16* pAh = Ahb + (size_t)(tm + lrow) * lda + lg;
    const __nv_bfloat16* pAl = Alb + (size_t)(tm + lrow) * lda + lg;
    const __nv_bfloat16* pBh = Bhb + (size_t)(tn + lrow) * ldb + lg;
    const __nv_bfloat16* pBl = Blb + (size_t)(tn + lrow) * ldb + lg;
    const uint32_t sbase = smem_u32(smem);
    const uint32_t doff  = (lrow * LDT + lg) * 2;

    float acc[4][4][4];
    #pragma unroll
    for (int i = 0; i < 4; i++)
        #pragma unroll
        for (int j = 0; j < 4; j++)
            #pragma unroll
            for (int t = 0; t < 4; t++) acc[i][j][t] = 0.f;

    auto issue = [&](int c) {
        const uint32_t sb = sbase + (c & 1) * STAGE_BYS + doff;
        const int k0 = c * BK;
        cp16(sb + SP_AH * 2,      pAh + k0);
        cp16(sb + SP_AH * 2 + 16, pAh + k0 + 8);
        cp16(sb + SP_AL * 2,      pAl + k0);
        cp16(sb + SP_AL * 2 + 16, pAl + k0 + 8);
        cp16(sb + SP_BH * 2,      pBh + k0);
        cp16(sb + SP_BH * 2 + 16, pBh + k0 + 8);
        cp16(sb + SP_BL * 2,      pBl + k0);
        cp16(sb + SP_BL * 2 + 16, pBl + k0 + 8);
    };

    const int nc = K / BK;
    issue(0);
    asm volatile("cp.async.commit_group;");

    const int arow = wm + (lane >> 2);
    const int brow = wn + (lane >> 2);
    const int kcol = (lane & 3) * 2;

    for (int c = 0; c < nc; ++c) {
        asm volatile("cp.async.wait_group 0;");
        __syncthreads();
        if (c + 1 < nc) issue(c + 1);
        asm volatile("cp.async.commit_group;");

        const __nv_bfloat16* st  = smem + (c & 1) * STAGE_ELS;
        const __nv_bfloat16* sAh = st + SP_AH;
        const __nv_bfloat16* sAl = st + SP_AL;
        const __nv_bfloat16* sBh = st + SP_BH;
        const __nv_bfloat16* sBl = st + SP_BL;

        #pragma unroll
        for (int ks = 0; ks < 2; ++ks) {
            const int kk = ks * 16 + kcol;
            uint32_t ah[4][4], al_[4][4];
            #pragma unroll
            for (int i = 0; i < 4; i++) {
                int base = (arow + i * 16) * LDT + kk;
                ah[i][0]  = ld32s(sAh + base);
                ah[i][1]  = ld32s(sAh + base + 8 * LDT);
                ah[i][2]  = ld32s(sAh + base + 8);
                ah[i][3]  = ld32s(sAh + base + 8 * LDT + 8);
                al_[i][0] = ld32s(sAl + base);
                al_[i][1] = ld32s(sAl + base + 8 * LDT);
                al_[i][2] = ld32s(sAl + base + 8);
                al_[i][3] = ld32s(sAl + base + 8 * LDT + 8);
            }
            #pragma unroll
            for (int j = 0; j < 4; j++) {
                int base = (brow + j * 8) * LDT + kk;
                uint32_t bh[2], bl_[2];
                bh[0]  = ld32s(sBh + base);
                bh[1]  = ld32s(sBh + base + 8);
                bl_[0] = ld32s(sBl + base);
                bl_[1] = ld32s(sBl + base + 8);
                #pragma unroll
                for (int i = 0; i < 4; i++) {
                    mma16816(acc[i][j], ah[i],  bh);
                    mma16816(acc[i][j], al_[i], bh);
                    mma16816(acc[i][j], ah[i],  bl_);
                }
            }
        }
    }

    float* cfp = Cf + (size_t)blockIdx.z * sC_;
    #pragma unroll
    for (int i = 0; i < 4; i++) {
        const int r0 = tm + wm + i * 16 + (lane >> 2);
        #pragma unroll
        for (int j = 0; j < 4; j++) {
            const int cc = tn + wn + j * 8 + (lane & 3) * 2;
            *reinterpret_cast<float2*>(&cfp[(size_t)r0 * ldc + cc]) =
                make_float2(acc[i][j][0], acc[i][j][1]);
            *reinterpret_cast<float2*>(&cfp[(size_t)(r0 + 8) * ldc + cc]) =
                make_float2(acc[i][j][2], acc[i][j][3]);
        }
    }
}

// ---------------- transpose + split: fp32 [R,Cc] -> bf16 hi/lo [Cc,R] ------
__global__ void transpose_split(const float* __restrict__ in,
                                __nv_bfloat16* __restrict__ oh,
                                __nv_bfloat16* __restrict__ ol,
                                int R, int Cc, size_t sIn, size_t sOut)
{
    __shared__ float t[32][33];
    const float* ip = in + (size_t)blockIdx.z * sIn;
    int r0 = blockIdx.y * 32, c0 = blockIdx.x * 32;
    #pragma unroll
    for (int j = threadIdx.y; j < 32; j += 8)
        t[j][threadIdx.x] = ip[(size_t)(r0 + j) * Cc + c0 + threadIdx.x];
    __syncthreads();
    #pragma unroll
    for (int j = threadIdx.y; j < 32; j += 8) {
        float f = t[threadIdx.x][j];
        __nv_bfloat16 h = __float2bfloat16(f);
        __nv_bfloat16 l = __float2bfloat16(f - __bfloat162float(h));
        size_t idx = (size_t)blockIdx.z * sOut + (size_t)(c0 + j) * R + r0 + threadIdx.x;
        oh[idx] = h;
        ol[idx] = l;
    }
}

// ---------------- transpose two bf16 planes: [R,Cc] -> [Cc,R] --------------
__global__ void transpose_b2(const __nv_bfloat16* __restrict__ ih,
                             const __nv_bfloat16* __restrict__ il,
                             __nv_bfloat16* __restrict__ oh,
                             __nv_bfloat16* __restrict__ ol,
                             int R, int Cc, size_t sIn, size_t sOut)
{
    __shared__ __nv_bfloat16 th[32][34], tl[32][34];
    const __nv_bfloat16* ihp = ih + (size_t)blockIdx.z * sIn;
    const __nv_bfloat16* ilp = il + (size_t)blockIdx.z * sIn;
    int r0 = blockIdx.y * 32, c0 = blockIdx.x * 32;
    #pragma unroll
    for (int j = threadIdx.y; j < 32; j += 8) {
        size_t s = (size_t)(r0 + j) * Cc + c0 + threadIdx.x;
        th[j][threadIdx.x] = ihp[s];
        tl[j][threadIdx.x] = ilp[s];
    }
    __syncthreads();
    #pragma unroll
    for (int j = threadIdx.y; j < 32; j += 8) {
        size_t d = (size_t)blockIdx.z * sOut + (size_t)(c0 + j) * R + r0 + threadIdx.x;
        oh[d] = th[threadIdx.x][j];
        ol[d] = tl[threadIdx.x][j];
    }
}

// ---------------- elementwise split fp32 -> bf16 hi/lo ---------------------
__global__ void split_w(const float* __restrict__ in,
                        __nv_bfloat16* __restrict__ oh,
                        __nv_bfloat16* __restrict__ ol, int n)
{
    int i = blockIdx.x * blockDim.x + threadIdx.x;
    if (i >= n) return;
    float f = in[i];
    __nv_bfloat16 h = __float2bfloat16(f);
    oh[i] = h;
    ol[i] = __float2bfloat16(f - __bfloat162float(h));
}

// ---------------- softmax (fp32 in, bf16 hi/lo out), rows of 512 -----------
__global__ void softmax_split(const float* __restrict__ S,
                              __nv_bfloat16* __restrict__ oh,
                              __nv_bfloat16* __restrict__ ol, float scale)
{
    int warp = (blockIdx.x * blockDim.x + threadIdx.x) >> 5;
    int lane = threadIdx.x & 31;
    if (warp >= B_ * C_) return;
    const float* row = S + (size_t)warp * C_;

    float vals[C_ / 32];
    float m = -1e30f;
    #pragma unroll
    for (int t = 0; t < C_ / 32; t++) {
        vals[t] = row[lane + t * 32] * scale;
        m = fmaxf(m, vals[t]);
    }
    #pragma unroll
    for (int o = 16; o; o >>= 1) m = fmaxf(m, __shfl_xor_sync(0xffffffffu, m, o));
    float s = 0.f;
    #pragma unroll
    for (int t = 0; t < C_ / 32; t++) { vals[t] = __expf(vals[t] - m); s += vals[t]; }
    #pragma unroll
    for (int o = 16; o; o >>= 1) s += __shfl_xor_sync(0xffffffffu, s, o);
    float inv = 1.f / s;
    #pragma unroll
    for (int t = 0; t < C_ / 32; t++) {
        float p = vals[t] * inv;
        __nv_bfloat16 h = __float2bfloat16(p);
        size_t idx = (size_t)warp * C_ + lane + t * 32;
        oh[idx] = h;
        ol[idx] = __float2bfloat16(p - __bfloat162float(h));
    }
}

// ---------------- launcher ----------------
extern "C" void kernel_launch(void* const* d_in, const int* in_sizes, int n_in,
                              void* d_out, int out_size)
{
    const float* x      = (const float*)d_in[0];
    const float* w_qkv  = (const float*)d_in[1];
    const float* b_qkv  = (const float*)d_in[2];
    const float* w_proj = (const float*)d_in[3];
    const float* b_proj = (const float*)d_in[4];
    float* out = (float*)d_out;

    __nv_bfloat16 *qh, *ql, *xTh, *xTl, *vTh, *vTl, *ah, *al, *wqh, *wql, *wph, *wpl;
    float *S;
    cudaGetSymbolAddress((void**)&qh,  g_qh);
    cudaGetSymbolAddress((void**)&ql,  g_ql);
    cudaGetSymbolAddress((void**)&xTh, g_xTh);
    cudaGetSymbolAddress((void**)&xTl, g_xTl);
    cudaGetSymbolAddress((void**)&vTh, g_vTh);
    cudaGetSymbolAddress((void**)&vTl, g_vTl);
    cudaGetSymbolAddress((void**)&S,   g_S);
    cudaGetSymbolAddress((void**)&ah,  g_ah);
    cudaGetSymbolAddress((void**)&al,  g_al);
    cudaGetSymbolAddress((void**)&wqh, g_wqh);
    cudaGetSymbolAddress((void**)&wql, g_wql);
    cudaGetSymbolAddress((void**)&wph, g_wph);
    cudaGetSymbolAddress((void**)&wpl, g_wpl);

    cudaFuncSetAttribute(gemm_big<true,  true>,  cudaFuncAttributeMaxDynamicSharedMemorySize, SMEM_BY2);
    cudaFuncSetAttribute(gemm_big<false, true>,  cudaFuncAttributeMaxDynamicSharedMemorySize, SMEM_BY2);
    cudaFuncSetAttribute(gemm_big<true,  false>, cudaFuncAttributeMaxDynamicSharedMemorySize, SMEM_BY2);
    cudaFuncSetAttribute(gemm_s, cudaFuncAttributeMaxDynamicSharedMemorySize, SMEM_BYS);

    const float scale = 1.0f / sqrtf((float)C_);
    dim3 tblk(32, 8);

    // 0) split weights
    split_w<<<(O3 * C_ + 255) / 256, 256>>>(w_qkv, wqh, wql, O3 * C_);
    split_w<<<(C_ * C_ + 255) / 256, 256>>>(w_proj, wph, wpl, C_ * C_);

    // 1) xT hi/lo: x[b,c,n] -> [b,n,c]
    transpose_split<<<dim3(N_ / 32, C_ / 32, B_), tblk>>>(
        x, xTh, xTl, C_, N_, (size_t)C_ * N_, (size_t)N_ * C_);

    // 2) qkv = w_qkv @ xT^T + b  -> bf16 hi/lo [b,1536,9216]
    gemm_big<true, true><<<dim3(N_ / BN2, O3 / BM2, B_), 512, SMEM_BY2>>>(
        wqh, wql, xTh, xTl, nullptr, qh, ql, b_qkv,
        C_, C_, C_, N_,
        0, (size_t)N_ * C_, (size_t)O3 * N_);

    // 3) vT hi/lo: v[b,d,n] -> [b,n,d]
    transpose_b2<<<dim3(N_ / 32, C_ / 32, B_), tblk>>>(
        qh + (size_t)2 * C_ * N_, ql + (size_t)2 * C_ * N_, vTh, vTl,
        C_, N_, (size_t)O3 * N_, (size_t)N_ * C_);

    // 4) S = q @ k^T (fp32), K=9216
    gemm_s<<<dim3(C_ / 128, C_ / 128, B_), 256, SMEM_BYS>>>(
        qh, ql, qh + (size_t)C_ * N_, ql + (size_t)C_ * N_, S,
        N_, N_, N_, C_,
        (size_t)O3 * N_, (size_t)O3 * N_, (size_t)C_ * C_);

    // 5) softmax -> attn hi/lo
    softmax_split<<<(B_ * C_ * 32 + 255) / 256, 256>>>(S, ah, al, scale);

    // 6) o1T[b,n,c] = vT[b,n,:] @ attn[b,c,:]  -> bf16 hi/lo (reuse xT buffers)
    gemm_big<false, true><<<dim3(C_ / BN2, N_ / BM2, B_), 512, SMEM_BY2>>>(
        vTh, vTl, ah, al, nullptr, xTh, xTl, nullptr,
        C_, C_, C_, C_,
        (size_t)N_ * C_, (size_t)C_ * C_, (size_t)N_ * C_);

    // 7) out = w_proj @ o1T^T + b (fp32)
    gemm_big<true, false><<<dim3(N_ / BN2, C_ / BM2, B_), 512, SMEM_BY2>>>(
        wph, wpl, xTh, xTl, out, nullptr, nullptr, b_proj,
        C_, C_, C_, N_,
        0, (size_t)N_ * C_, (size_t)C_ * N_);
}

// round 6
// speedup vs baseline: 2.3718x; 1.0833x over previous
#include <cuda_runtime.h>
#include <cuda_bf16.h>
#include <math.h>
#include <stdint.h>

// ---------------- problem constants ----------------
constexpr int B_ = 8, C_ = 512, H_ = 96, W_ = 96;
constexpr int N_ = H_ * W_;    // 9216
constexpr int O3 = 3 * C_;     // 1536

// ---------------- scratch: bf16 hi/lo planes ----------------
__device__ __align__(256) __nv_bfloat16 g_qh [(size_t)B_ * O3 * N_];
__device__ __align__(256) __nv_bfloat16 g_ql [(size_t)B_ * O3 * N_];
__device__ __align__(256) __nv_bfloat16 g_xTh[(size_t)B_ * N_ * C_];  // reused as o1T
__device__ __align__(256) __nv_bfloat16 g_xTl[(size_t)B_ * N_ * C_];
__device__ __align__(256) __nv_bfloat16 g_vTh[(size_t)B_ * N_ * C_];
__device__ __align__(256) __nv_bfloat16 g_vTl[(size_t)B_ * N_ * C_];
__device__ __align__(256) float         g_S  [(size_t)B_ * C_ * C_];
__device__ __align__(256) __nv_bfloat16 g_ah [(size_t)B_ * C_ * C_];
__device__ __align__(256) __nv_bfloat16 g_al [(size_t)B_ * C_ * C_];
__device__ __align__(256) __nv_bfloat16 g_wqh[(size_t)O3 * C_];
__device__ __align__(256) __nv_bfloat16 g_wql[(size_t)O3 * C_];
__device__ __align__(256) __nv_bfloat16 g_wph[(size_t)C_ * C_];
__device__ __align__(256) __nv_bfloat16 g_wpl[(size_t)C_ * C_];

// ---------------- common helpers ----------------
#define BK 32
#define LDT 40   // smem row stride in bf16 (BK + 8 pad)

__device__ __forceinline__ uint32_t smem_u32(const void* p) {
    uint32_t a;
    asm("{ .reg .u64 t; cvta.to.shared.u64 t, %1; cvt.u32.u64 %0, t; }"
        : "=r"(a) : "l"(p));
    return a;
}
__device__ __forceinline__ void cp16(uint32_t dst, const void* src) {
    asm volatile("cp.async.cg.shared.global [%0], [%1], 16;"
                 :: "r"(dst), "l"(src));
}
__device__ __forceinline__ void mma16816(float* d, const uint32_t* a,
                                         const uint32_t* b) {
    asm volatile(
        "mma.sync.aligned.m16n8k16.row.col.f32.bf16.bf16.f32 "
        "{%0,%1,%2,%3}, {%4,%5,%6,%7}, {%8,%9}, {%0,%1,%2,%3};"
        : "+f"(d[0]), "+f"(d[1]), "+f"(d[2]), "+f"(d[3])
        : "r"(a[0]), "r"(a[1]), "r"(a[2]), "r"(a[3]), "r"(b[0]), "r"(b[1]));
}
__device__ __forceinline__ void ldm4(uint32_t* r, uint32_t a) {
    asm volatile("ldmatrix.sync.aligned.m8n8.x4.shared.b16 {%0,%1,%2,%3}, [%4];"
        : "=r"(r[0]), "=r"(r[1]), "=r"(r[2]), "=r"(r[3]) : "r"(a));
}
__device__ __forceinline__ uint32_t pack2(__nv_bfloat16 a, __nv_bfloat16 b) {
    return (uint32_t)__bfloat16_as_ushort(a) |
           ((uint32_t)__bfloat16_as_ushort(b) << 16);
}

// lane offsets (bf16 elem units) for ldmatrix addressing
// A tile (m16 x k16 as 4 8x8): row = (l&7)+((l>>3)&1)*8 ; kofs = ((l>>4)&1)*8
__device__ __forceinline__ int laneA_off(int lane) {
    return ((lane & 7) + ((lane >> 3) & 1) * 8) * LDT + ((lane >> 4) & 1) * 8;
}
// B pair-of-j tile (n16 x k16): row = (l&7)+((l>>4)&1)*8 ; kofs = ((l>>3)&1)*8
__device__ __forceinline__ int laneB_off(int lane) {
    return ((lane & 7) + ((lane >> 4) & 1) * 8) * LDT + ((lane >> 3) & 1) * 8;
}

// ================= BIG kernel: 128(M) x 256(N), 512 threads, 3-stage ======
#define BM2 128
#define BN2 256
#define NST2 3
#define P_AH 0
#define P_AL (128 * LDT)
#define P_BH (256 * LDT)
#define P_BL (512 * LDT)
#define STAGE_EL2 (768 * LDT)
#define STAGE_BY2 (STAGE_EL2 * 2)             // 61440 B
#define SMEM_BY2 (NST2 * STAGE_BY2)           // 184320 B

template<bool HASBIAS, bool SPLITOUT>
__global__ __launch_bounds__(512)
void gemm_big(const __nv_bfloat16* __restrict__ Ah, const __nv_bfloat16* __restrict__ Al,
              const __nv_bfloat16* __restrict__ Bh, const __nv_bfloat16* __restrict__ Bl,
              float* __restrict__ Cf,
              __nv_bfloat16* __restrict__ Ch, __nv_bfloat16* __restrict__ Cl,
              const float* __restrict__ bias,
              int K, int lda, int ldb, int ldc,
              size_t sA_, size_t sB_, size_t sC_)
{
    extern __shared__ __nv_bfloat16 smem[];
    const int tid  = threadIdx.x;
    const int warp = tid >> 5;
    const int lane = tid & 31;
    const int wm   = (warp >> 3) * 64;   // 2 warps in M
    const int wn   = (warp & 7) * 32;    // 8 warps in N
    const int tm   = blockIdx.y * BM2;
    const int tn   = blockIdx.x * BN2;

    const __nv_bfloat16* Ahb = Ah + (size_t)blockIdx.z * sA_;
    const __nv_bfloat16* Alb = Al + (size_t)blockIdx.z * sA_;
    const __nv_bfloat16* Bhb = Bh + (size_t)blockIdx.z * sB_;
    const __nv_bfloat16* Blb = Bl + (size_t)blockIdx.z * sB_;

    const int arow0 = tid >> 2, ag0 = (tid & 3) * 8;
    const int brow1 = tid >> 2, bg1 = (tid & 3) * 8;
    const int brow2 = (tid + 512) >> 2, bg2 = bg1;

    const __nv_bfloat16* pAh  = Ahb + (size_t)(tm + arow0) * lda + ag0;
    const __nv_bfloat16* pAl  = Alb + (size_t)(tm + arow0) * lda + ag0;
    const __nv_bfloat16* pB1h = Bhb + (size_t)(tn + brow1) * ldb + bg1;
    const __nv_bfloat16* pB1l = Blb + (size_t)(tn + brow1) * ldb + bg1;
    const __nv_bfloat16* pB2h = Bhb + (size_t)(tn + brow2) * ldb + bg2;
    const __nv_bfloat16* pB2l = Blb + (size_t)(tn + brow2) * ldb + bg2;

    const uint32_t sbase = smem_u32(smem);
    const uint32_t dA  = (arow0 * LDT + ag0) * 2;
    const uint32_t dB1 = (brow1 * LDT + bg1) * 2;
    const uint32_t dB2 = (brow2 * LDT + bg2) * 2;

    const int lA = laneA_off(lane);
    const int lB = laneB_off(lane);

    float acc[4][4][4];
    #pragma unroll
    for (int i = 0; i < 4; i++)
        #pragma unroll
        for (int j = 0; j < 4; j++)
            #pragma unroll
            for (int t = 0; t < 4; t++) acc[i][j][t] = 0.f;

    auto issue = [&](int c) {
        const uint32_t sb = sbase + (c % NST2) * STAGE_BY2;
        const int k0 = c * BK;
        cp16(sb + P_AH * 2 + dA,  pAh + k0);
        cp16(sb + P_AL * 2 + dA,  pAl + k0);
        cp16(sb + P_BH * 2 + dB1, pB1h + k0);
        cp16(sb + P_BL * 2 + dB1, pB1l + k0);
        cp16(sb + P_BH * 2 + dB2, pB2h + k0);
        cp16(sb + P_BL * 2 + dB2, pB2l + k0);
    };

    const int nc = K / BK;
    issue(0);
    asm volatile("cp.async.commit_group;");
    issue(1);
    asm volatile("cp.async.commit_group;");

    for (int c = 0; c < nc; ++c) {
        asm volatile("cp.async.wait_group 1;");
        __syncthreads();
        if (c + 2 < nc) issue(c + 2);
        asm volatile("cp.async.commit_group;");

        const uint32_t stb = sbase + (c % NST2) * STAGE_BY2;
        #pragma unroll
        for (int ks = 0; ks < 2; ++ks) {
            const int kofs = ks * 16;
            uint32_t ah[4][4], al_[4][4];
            #pragma unroll
            for (int i = 0; i < 4; i++) {
                uint32_t ao = ((wm + i * 16) * LDT + lA + kofs) * 2;
                ldm4(ah[i],  stb + P_AH * 2 + ao);
                ldm4(al_[i], stb + P_AL * 2 + ao);
            }
            #pragma unroll
            for (int jp = 0; jp < 2; ++jp) {
                uint32_t bo = ((wn + jp * 16) * LDT + lB + kofs) * 2;
                uint32_t bh[4], bl_[4];
                ldm4(bh,  stb + P_BH * 2 + bo);
                ldm4(bl_, stb + P_BL * 2 + bo);
                const int j0 = jp * 2, j1 = jp * 2 + 1;
                #pragma unroll
                for (int i = 0; i < 4; i++) { mma16816(acc[i][j0], ah[i],  bh);     }
                #pragma unroll
                for (int i = 0; i < 4; i++) { mma16816(acc[i][j1], ah[i],  bh + 2); }
                #pragma unroll
                for (int i = 0; i < 4; i++) { mma16816(acc[i][j0], al_[i], bh);     }
                #pragma unroll
                for (int i = 0; i < 4; i++) { mma16816(acc[i][j1], al_[i], bh + 2); }
                #pragma unroll
                for (int i = 0; i < 4; i++) { mma16816(acc[i][j0], ah[i],  bl_);    }
                #pragma unroll
                for (int i = 0; i < 4; i++) { mma16816(acc[i][j1], ah[i],  bl_ + 2);}
            }
        }
    }

    // ---------------- epilogue ----------------
    #pragma unroll
    for (int i = 0; i < 4; i++) {
        const int r0 = tm + wm + i * 16 + (lane >> 2);
        float bv0 = 0.f, bv1 = 0.f;
        if (HASBIAS) { bv0 = bias[r0]; bv1 = bias[r0 + 8]; }
        #pragma unroll
        for (int j = 0; j < 4; j++) {
            const int cc = tn + wn + j * 8 + (lane & 3) * 2;
            float d0 = acc[i][j][0] + bv0, d1 = acc[i][j][1] + bv0;
            float d2 = acc[i][j][2] + bv1, d3 = acc[i][j][3] + bv1;
            if (SPLITOUT) {
                __nv_bfloat16* chp = Ch + (size_t)blockIdx.z * sC_;
                __nv_bfloat16* clp = Cl + (size_t)blockIdx.z * sC_;
                __nv_bfloat16 h0 = __float2bfloat16(d0), h1 = __float2bfloat16(d1);
                __nv_bfloat16 h2 = __float2bfloat16(d2), h3 = __float2bfloat16(d3);
                __nv_bfloat16 l0 = __float2bfloat16(d0 - __bfloat162float(h0));
                __nv_bfloat16 l1 = __float2bfloat16(d1 - __bfloat162float(h1));
                __nv_bfloat16 l2 = __float2bfloat16(d2 - __bfloat162float(h2));
                __nv_bfloat16 l3 = __float2bfloat16(d3 - __bfloat162float(h3));
                *reinterpret_cast<uint32_t*>(&chp[(size_t)r0 * ldc + cc])       = pack2(h0, h1);
                *reinterpret_cast<uint32_t*>(&clp[(size_t)r0 * ldc + cc])       = pack2(l0, l1);
                *reinterpret_cast<uint32_t*>(&chp[(size_t)(r0 + 8) * ldc + cc]) = pack2(h2, h3);
                *reinterpret_cast<uint32_t*>(&clp[(size_t)(r0 + 8) * ldc + cc]) = pack2(l2, l3);
            } else {
                float* cfp = Cf + (size_t)blockIdx.z * sC_;
                *reinterpret_cast<float2*>(&cfp[(size_t)r0 * ldc + cc])       = make_float2(d0, d1);
                *reinterpret_cast<float2*>(&cfp[(size_t)(r0 + 8) * ldc + cc]) = make_float2(d2, d3);
            }
        }
    }
}

// ================= S kernel: 128x128, 256 threads, 2-stage (2 CTA/SM) =====
#define SP_AH 0
#define SP_AL (128 * LDT)
#define SP_BH (256 * LDT)
#define SP_BL (384 * LDT)
#define STAGE_ELS (512 * LDT)
#define STAGE_BYS (STAGE_ELS * 2)             // 40960 B
#define NSTS 2
#define SMEM_BYS (NSTS * STAGE_BYS)           // 81920 B

__global__ __launch_bounds__(256)
void gemm_s(const __nv_bfloat16* __restrict__ Ah, const __nv_bfloat16* __restrict__ Al,
            const __nv_bfloat16* __restrict__ Bh, const __nv_bfloat16* __restrict__ Bl,
            float* __restrict__ Cf,
            int K, int lda, int ldb, int ldc,
            size_t sA_, size_t sB_, size_t sC_)
{
    extern __shared__ __nv_bfloat16 smem[];
    const int tid  = threadIdx.x;
    const int warp = tid >> 5;
    const int lane = tid & 31;
    const int wm   = (warp >> 2) * 64;
    const int wn   = (warp & 3) * 32;
    const int tm   = blockIdx.y * 128;
    const int tn   = blockIdx.x * 128;

    const __nv_bfloat16* Ahb = Ah + (size_t)blockIdx.z * sA_;
    const __nv_bfloat16* Alb = Al + (size_t)blockIdx.z * sA_;
    const __nv_bfloat16* Bhb = Bh + (size_t)blockIdx.z * sB_;
    const __nv_bfloat16* Blb = Bl + (size_t)blockIdx.z * sB_;

    const int lrow = tid >> 1;
    const int lg   = (tid & 1) * 16;
    const __nv_bfloat16* pAh = Ahb + (size_t)(tm + lrow) * lda + lg;
    const __nv_bfloat16* pAl = Alb + (size_t)(tm + lrow) * lda + lg;
    const __nv_bfloat16* pBh = Bhb + (size_t)(tn + lrow) * ldb + lg;
    const __nv_bfloat16* pBl = Blb + (size_t)(tn + lrow) * ldb + lg;
    const uint32_t sbase = smem_u32(smem);
    const uint32_t doff  = (lrow * LDT + lg) * 2;

    const int lA = laneA_off(lane);
    const int lB = laneB_off(lane);

    float acc[4][4][4];
    #pragma unroll
    for (int i = 0; i < 4; i++)
        #pragma unroll
        for (int j = 0; j < 4; j++)
            #pragma unroll
            for (int t = 0; t < 4; t++) acc[i][j][t] = 0.f;

    auto issue = [&](int c) {
        const uint32_t sb = sbase + (c & 1) * STAGE_BYS + doff;
        const int k0 = c * BK;
        cp16(sb + SP_AH * 2,      pAh + k0);
        cp16(sb + SP_AH * 2 + 16, pAh + k0 + 8);
        cp16(sb + SP_AL * 2,      pAl + k0);
        cp16(sb + SP_AL * 2 + 16, pAl + k0 + 8);
        cp16(sb + SP_BH * 2,      pBh + k0);
        cp16(sb + SP_BH * 2 + 16, pBh + k0 + 8);
        cp16(sb + SP_BL * 2,      pBl + k0);
        cp16(sb + SP_BL * 2 + 16, pBl + k0 + 8);
    };

    const int nc = K / BK;
    issue(0);
    asm volatile("cp.async.commit_group;");

    for (int c = 0; c < nc; ++c) {
        asm volatile("cp.async.wait_group 0;");
        __syncthreads();
        if (c + 1 < nc) issue(c + 1);
        asm volatile("cp.async.commit_group;");

        const uint32_t stb = sbase + (c & 1) * STAGE_BYS;
        #pragma unroll
        for (int ks = 0; ks < 2; ++ks) {
            const int kofs = ks * 16;
            uint32_t ah[4][4], al_[4][4];
            #pragma unroll
            for (int i = 0; i < 4; i++) {
                uint32_t ao = ((wm + i * 16) * LDT + lA + kofs) * 2;
                ldm4(ah[i],  stb + SP_AH * 2 + ao);
                ldm4(al_[i], stb + SP_AL * 2 + ao);
            }
            #pragma unroll
            for (int jp = 0; jp < 2; ++jp) {
                uint32_t bo = ((wn + jp * 16) * LDT + lB + kofs) * 2;
                uint32_t bh[4], bl_[4];
                ldm4(bh,  stb + SP_BH * 2 + bo);
                ldm4(bl_, stb + SP_BL * 2 + bo);
                const int j0 = jp * 2, j1 = jp * 2 + 1;
                #pragma unroll
                for (int i = 0; i < 4; i++) { mma16816(acc[i][j0], ah[i],  bh);     }
                #pragma unroll
                for (int i = 0; i < 4; i++) { mma16816(acc[i][j1], ah[i],  bh + 2); }
                #pragma unroll
                for (int i = 0; i < 4; i++) { mma16816(acc[i][j0], al_[i], bh);     }
                #pragma unroll
                for (int i = 0; i < 4; i++) { mma16816(acc[i][j1], al_[i], bh + 2); }
                #pragma unroll
                for (int i = 0; i < 4; i++) { mma16816(acc[i][j0], ah[i],  bl_);    }
                #pragma unroll
                for (int i = 0; i < 4; i++) { mma16816(acc[i][j1], ah[i],  bl_ + 2);}
            }
        }
    }

    float* cfp = Cf + (size_t)blockIdx.z * sC_;
    #pragma unroll
    for (int i = 0; i < 4; i++) {
        const int r0 = tm + wm + i * 16 + (lane >> 2);
        #pragma unroll
        for (int j = 0; j < 4; j++) {
            const int cc = tn + wn + j * 8 + (lane & 3) * 2;
            *reinterpret_cast<float2*>(&cfp[(size_t)r0 * ldc + cc]) =
                make_float2(acc[i][j][0], acc[i][j][1]);
            *reinterpret_cast<float2*>(&cfp[(size_t)(r0 + 8) * ldc + cc]) =
                make_float2(acc[i][j][2], acc[i][j][3]);
        }
    }
}

// ---------------- transpose + split: fp32 [R,Cc] -> bf16 hi/lo [Cc,R] ------
__global__ void transpose_split(const float* __restrict__ in,
                                __nv_bfloat16* __restrict__ oh,
                                __nv_bfloat16* __restrict__ ol,
                                int R, int Cc, size_t sIn, size_t sOut)
{
    __shared__ float t[32][33];
    const float* ip = in + (size_t)blockIdx.z * sIn;
    int r0 = blockIdx.y * 32, c0 = blockIdx.x * 32;
    #pragma unroll
    for (int j = threadIdx.y; j < 32; j += 8)
        t[j][threadIdx.x] = ip[(size_t)(r0 + j) * Cc + c0 + threadIdx.x];
    __syncthreads();
    #pragma unroll
    for (int j = threadIdx.y; j < 32; j += 8) {
        float f = t[threadIdx.x][j];
        __nv_bfloat16 h = __float2bfloat16(f);
        __nv_bfloat16 l = __float2bfloat16(f - __bfloat162float(h));
        size_t idx = (size_t)blockIdx.z * sOut + (size_t)(c0 + j) * R + r0 + threadIdx.x;
        oh[idx] = h;
        ol[idx] = l;
    }
}

// ---------------- transpose two bf16 planes: [R,Cc] -> [Cc,R] --------------
__global__ void transpose_b2(const __nv_bfloat16* __restrict__ ih,
                             const __nv_bfloat16* __restrict__ il,
                             __nv_bfloat16* __restrict__ oh,
                             __nv_bfloat16* __restrict__ ol,
                             int R, int Cc, size_t sIn, size_t sOut)
{
    __shared__ __nv_bfloat16 th[32][34], tl[32][34];
    const __nv_bfloat16* ihp = ih + (size_t)blockIdx.z * sIn;
    const __nv_bfloat16* ilp = il + (size_t)blockIdx.z * sIn;
    int r0 = blockIdx.y * 32, c0 = blockIdx.x * 32;
    #pragma unroll
    for (int j = threadIdx.y; j < 32; j += 8) {
        size_t s = (size_t)(r0 + j) * Cc + c0 + threadIdx.x;
        th[j][threadIdx.x] = ihp[s];
        tl[j][threadIdx.x] = ilp[s];
    }
    __syncthreads();
    #pragma unroll
    for (int j = threadIdx.y; j < 32; j += 8) {
        size_t d = (size_t)blockIdx.z * sOut + (size_t)(c0 + j) * R + r0 + threadIdx.x;
        oh[d] = th[threadIdx.x][j];
        ol[d] = tl[threadIdx.x][j];
    }
}

// ---------------- elementwise split fp32 -> bf16 hi/lo ---------------------
__global__ void split_w(const float* __restrict__ in,
                        __nv_bfloat16* __restrict__ oh,
                        __nv_bfloat16* __restrict__ ol, int n)
{
    int i = blockIdx.x * blockDim.x + threadIdx.x;
    if (i >= n) return;
    float f = in[i];
    __nv_bfloat16 h = __float2bfloat16(f);
    oh[i] = h;
    ol[i] = __float2bfloat16(f - __bfloat162float(h));
}

// ---------------- softmax (fp32 in, bf16 hi/lo out), rows of 512 -----------
__global__ void softmax_split(const float* __restrict__ S,
                              __nv_bfloat16* __restrict__ oh,
                              __nv_bfloat16* __restrict__ ol, float scale)
{
    int warp = (blockIdx.x * blockDim.x + threadIdx.x) >> 5;
    int lane = threadIdx.x & 31;
    if (warp >= B_ * C_) return;
    const float* row = S + (size_t)warp * C_;

    float vals[C_ / 32];
    float m = -1e30f;
    #pragma unroll
    for (int t = 0; t < C_ / 32; t++) {
        vals[t] = row[lane + t * 32] * scale;
        m = fmaxf(m, vals[t]);
    }
    #pragma unroll
    for (int o = 16; o; o >>= 1) m = fmaxf(m, __shfl_xor_sync(0xffffffffu, m, o));
    float s = 0.f;
    #pragma unroll
    for (int t = 0; t < C_ / 32; t++) { vals[t] = __expf(vals[t] - m); s += vals[t]; }
    #pragma unroll
    for (int o = 16; o; o >>= 1) s += __shfl_xor_sync(0xffffffffu, s, o);
    float inv = 1.f / s;
    #pragma unroll
    for (int t = 0; t < C_ / 32; t++) {
        float p = vals[t] * inv;
        __nv_bfloat16 h = __float2bfloat16(p);
        size_t idx = (size_t)warp * C_ + lane + t * 32;
        oh[idx] = h;
        ol[idx] = __float2bfloat16(p - __bfloat162float(h));
    }
}

// ---------------- launcher ----------------
extern "C" void kernel_launch(void* const* d_in, const int* in_sizes, int n_in,
                              void* d_out, int out_size)
{
    const float* x      = (const float*)d_in[0];
    const float* w_qkv  = (const float*)d_in[1];
    const float* b_qkv  = (const float*)d_in[2];
    const float* w_proj = (const float*)d_in[3];
    const float* b_proj = (const float*)d_in[4];
    float* out = (float*)d_out;

    __nv_bfloat16 *qh, *ql, *xTh, *xTl, *vTh, *vTl, *ah, *al, *wqh, *wql, *wph, *wpl;
    float *S;
    cudaGetSymbolAddress((void**)&qh,  g_qh);
    cudaGetSymbolAddress((void**)&ql,  g_ql);
    cudaGetSymbolAddress((void**)&xTh, g_xTh);
    cudaGetSymbolAddress((void**)&xTl, g_xTl);
    cudaGetSymbolAddress((void**)&vTh, g_vTh);
    cudaGetSymbolAddress((void**)&vTl, g_vTl);
    cudaGetSymbolAddress((void**)&S,   g_S);
    cudaGetSymbolAddress((void**)&ah,  g_ah);
    cudaGetSymbolAddress((void**)&al,  g_al);
    cudaGetSymbolAddress((void**)&wqh, g_wqh);
    cudaGetSymbolAddress((void**)&wql, g_wql);
    cudaGetSymbolAddress((void**)&wph, g_wph);
    cudaGetSymbolAddress((void**)&wpl, g_wpl);

    cudaFuncSetAttribute(gemm_big<true,  true>,  cudaFuncAttributeMaxDynamicSharedMemorySize, SMEM_BY2);
    cudaFuncSetAttribute(gemm_big<false, true>,  cudaFuncAttributeMaxDynamicSharedMemorySize, SMEM_BY2);
    cudaFuncSetAttribute(gemm_big<true,  false>, cudaFuncAttributeMaxDynamicSharedMemorySize, SMEM_BY2);
    cudaFuncSetAttribute(gemm_s, cudaFuncAttributeMaxDynamicSharedMemorySize, SMEM_BYS);

    const float scale = 1.0f / sqrtf((float)C_);
    dim3 tblk(32, 8);

    // 0) split weights
    split_w<<<(O3 * C_ + 255) / 256, 256>>>(w_qkv, wqh, wql, O3 * C_);
    split_w<<<(C_ * C_ + 255) / 256, 256>>>(w_proj, wph, wpl, C_ * C_);

    // 1) xT hi/lo: x[b,c,n] -> [b,n,c]
    transpose_split<<<dim3(N_ / 32, C_ / 32, B_), tblk>>>(
        x, xTh, xTl, C_, N_, (size_t)C_ * N_, (size_t)N_ * C_);

    // 2) qkv = w_qkv @ xT^T + b  -> bf16 hi/lo [b,1536,9216]
    gemm_big<true, true><<<dim3(N_ / BN2, O3 / BM2, B_), 512, SMEM_BY2>>>(
        wqh, wql, xTh, xTl, nullptr, qh, ql, b_qkv,
        C_, C_, C_, N_,
        0, (size_t)N_ * C_, (size_t)O3 * N_);

    // 3) vT hi/lo: v[b,d,n] -> [b,n,d]
    transpose_b2<<<dim3(N_ / 32, C_ / 32, B_), tblk>>>(
        qh + (size_t)2 * C_ * N_, ql + (size_t)2 * C_ * N_, vTh, vTl,
        C_, N_, (size_t)O3 * N_, (size_t)N_ * C_);

    // 4) S = q @ k^T (fp32), K=9216
    gemm_s<<<dim3(C_ / 128, C_ / 128, B_), 256, SMEM_BYS>>>(
        qh, ql, qh + (size_t)C_ * N_, ql + (size_t)C_ * N_, S,
        N_, N_, N_, C_,
        (size_t)O3 * N_, (size_t)O3 * N_, (size_t)C_ * C_);

    // 5) softmax -> attn hi/lo
    softmax_split<<<(B_ * C_ * 32 + 255) / 256, 256>>>(S, ah, al, scale);

    // 6) o1T[b,n,c] = vT[b,n,:] @ attn[b,c,:]  -> bf16 hi/lo (reuse xT buffers)
    gemm_big<false, true><<<dim3(C_ / BN2, N_ / BM2, B_), 512, SMEM_BY2>>>(
        vTh, vTl, ah, al, nullptr, xTh, xTl, nullptr,
        C_, C_, C_, C_,
        (size_t)N_ * C_, (size_t)C_ * C_, (size_t)N_ * C_);

    // 7) out = w_proj @ o1T^T + b (fp32)
    gemm_big<true, false><<<dim3(N_ / BN2, C_ / BM2, B_), 512, SMEM_BY2>>>(
        wph, wpl, xTh, xTl, out, nullptr, nullptr, b_proj,
        C_, C_, C_, N_,
        0, (size_t)N_ * C_, (size_t)C_ * N_);
}